// round 14
// baseline (speedup 1.0000x reference)
#include <cuda_runtime.h>
#include <cuda_bf16.h>
#include <math.h>
#include <stdint.h>

// ---------------- scratch (device globals; no allocs allowed) ----------------
__device__ float g_z[512 * 448];            // z padded to 448 cols (cols 432..447 = 0)
__device__ float g_part[18 * 512 * 512];    // split-K partials
__device__ float g_h1[512 * 512];           // relu(inter@pw0+pb0)
// W0 converted to bf16, SAME [k][n] layout (no transpose)
__device__ __nv_bfloat16 g_w0c[(size_t)186624 * 512];
// zero page for masked cp.async sources (static zero-init)
__device__ __align__(16) uint4 g_zero4[8];

// pack two fp32 -> bf16x2 (lo -> low half)
__device__ __forceinline__ uint32_t pack_bf16(float lo, float hi) {
    uint32_t r;
    asm("cvt.rn.bf16x2.f32 %0, %1, %2;" : "=r"(r) : "f"(hi), "f"(lo));
    return r;
}
__device__ __forceinline__ uint32_t hmul2(uint32_t a, uint32_t b) {
    uint32_t r;
    asm("mul.rn.bf16x2 %0, %1, %2;" : "=r"(r) : "r"(a), "r"(b));
    return r;
}
__device__ __forceinline__ uint32_t hadd2(uint32_t a, uint32_t b) {
    uint32_t r;
    asm("add.rn.bf16x2 %0, %1, %2;" : "=r"(r) : "r"(a), "r"(b));
    return r;
}
__device__ __forceinline__ uint32_t smem_u32(const void* p) {
    uint32_t a;
    asm("{ .reg .u64 t; cvta.to.shared.u64 t, %1; cvt.u32.u64 %0, t; }" : "=r"(a) : "l"(p));
    return a;
}
#define LDSM4T(R0, R1, R2, R3, ADDR)                                           \
    asm volatile("ldmatrix.sync.aligned.m8n8.x4.trans.shared.b16 {%0,%1,%2,%3}, [%4];" \
                 : "=r"(R0), "=r"(R1), "=r"(R2), "=r"(R3) : "r"(ADDR))
__device__ __forceinline__ void cpasync32(uint32_t dst, const void* src) {
    asm volatile(
        "cp.async.cg.shared.global [%0], [%1], 16;\n\t"
        "cp.async.cg.shared.global [%2], [%3], 16;"
        :: "r"(dst), "l"(src), "r"(dst + 16), "l"((const char*)src + 16) : "memory");
}
#define CP_COMMIT() asm volatile("cp.async.commit_group;" ::: "memory")
#define CP_WAIT2()  asm volatile("cp.async.wait_group 2;" ::: "memory")

// ---------------- kernel 0: elementwise convert W0 -> bf16 (streaming) ------
__global__ void convert_w0_kernel(const float* __restrict__ W0) {
    size_t i = ((size_t)blockIdx.x * 256 + threadIdx.x) * 16;
    float4 a = __ldcs((const float4*)(W0 + i));
    float4 b = __ldcs((const float4*)(W0 + i + 4));
    float4 c = __ldcs((const float4*)(W0 + i + 8));
    float4 d = __ldcs((const float4*)(W0 + i + 12));
    uint4 o0, o1;
    o0.x = pack_bf16(a.x, a.y); o0.y = pack_bf16(a.z, a.w);
    o0.z = pack_bf16(b.x, b.y); o0.w = pack_bf16(b.z, b.w);
    o1.x = pack_bf16(c.x, c.y); o1.y = pack_bf16(c.z, c.w);
    o1.z = pack_bf16(d.x, d.y); o1.w = pack_bf16(d.z, d.w);
    __stcs((uint4*)(g_w0c + i), o0);
    __stcs((uint4*)(g_w0c + i + 8), o1);
}

// ---------------- kernel 1: dense MLP (4 batch rows / block) ----------------
__global__ void dense_mlp_kernel(const float* __restrict__ x,
                                 const float* __restrict__ dw0, const float* __restrict__ db0,
                                 const float* __restrict__ dw1, const float* __restrict__ db1,
                                 const float* __restrict__ dw2, const float* __restrict__ db2,
                                 const float* __restrict__ dw3, const float* __restrict__ db3) {
    __shared__ float xs[4][13];
    __shared__ float h0[4][512];
    __shared__ float h1[4][256];
    __shared__ float h2[4][64];
    const int r0 = blockIdx.x * 4;
    const int tid = threadIdx.x;

    if (tid < 52) xs[tid / 13][tid % 13] = x[(r0 + tid / 13) * 13 + tid % 13];
    __syncthreads();

    #pragma unroll
    for (int jj = 0; jj < 2; jj++) {
        int j = tid + jj * 256;
        float a[4];
        float b = db0[j];
        #pragma unroll
        for (int r = 0; r < 4; r++) a[r] = b;
        #pragma unroll
        for (int i = 0; i < 13; i++) {
            float w = dw0[i * 512 + j];
            #pragma unroll
            for (int r = 0; r < 4; r++) a[r] += xs[r][i] * w;
        }
        #pragma unroll
        for (int r = 0; r < 4; r++) h0[r][j] = fmaxf(a[r], 0.f);
    }
    __syncthreads();

    {
        float a[4];
        float b = db1[tid];
        #pragma unroll
        for (int r = 0; r < 4; r++) a[r] = b;
        #pragma unroll 16
        for (int i = 0; i < 512; i++) {
            float w = dw1[i * 256 + tid];
            #pragma unroll
            for (int r = 0; r < 4; r++) a[r] += h0[r][i] * w;
        }
        #pragma unroll
        for (int r = 0; r < 4; r++) h1[r][tid] = fmaxf(a[r], 0.f);
    }
    __syncthreads();

    if (tid < 64) {
        float a[4];
        float b = db2[tid];
        #pragma unroll
        for (int r = 0; r < 4; r++) a[r] = b;
        #pragma unroll 16
        for (int i = 0; i < 256; i++) {
            float w = dw2[i * 64 + tid];
            #pragma unroll
            for (int r = 0; r < 4; r++) a[r] += h1[r][i] * w;
        }
        #pragma unroll
        for (int r = 0; r < 4; r++) h2[r][tid] = fmaxf(a[r], 0.f);
    }
    __syncthreads();

    if (tid < 16) {
        float a[4];
        float b = db3[tid];
        #pragma unroll
        for (int r = 0; r < 4; r++) a[r] = b;
        #pragma unroll
        for (int i = 0; i < 64; i++) {
            float w = dw3[i * 16 + tid];
            #pragma unroll
            for (int r = 0; r < 4; r++) a[r] += h2[r][i] * w;
        }
        #pragma unroll
        for (int r = 0; r < 4; r++) g_z[(size_t)(r0 + r) * 448 + tid] = a[r];
    }
    if (tid >= 64 && tid < 128) {
        int u = tid - 64;
        g_z[(size_t)(r0 + u / 16) * 448 + 432 + (u % 16)] = 0.f;
    }
}

// ---------------- kernel 2: embedding gather -> z[:,16:432] ----------------
__global__ void embed_kernel(const void* __restrict__ sp, const float* __restrict__ emb) {
    int t = blockIdx.x * blockDim.x + threadIdx.x;
    if (t >= 512 * 26) return;
    const int* si = (const int*)sp;
    bool is64 = (si[1] == 0 && si[3] == 0 && si[5] == 0);
    long long v = is64 ? ((const long long*)sp)[t] : (long long)si[t];
    int id = (int)((v + 1) % 100000);
    int b = t / 26, f = t - b * 26;
    const float4* src = (const float4*)(emb + ((size_t)f * 100000 + id) * 16);
    float4* dst = (float4*)(g_z + (size_t)b * 448 + 16 + f * 16);
    dst[0] = src[0]; dst[1] = src[1]; dst[2] = src[2]; dst[3] = src[3];
}

// ---------------- kernel 3: SYMMETRIC interaction GEMM ----------------------
// C[b,n] = sum_p z_p^2 W[p,p,n] + sum_{p<q} z_p z_q (W[p,q,n]+W[q,p,n]).
// Stage (p, window w) exists iff w >= floor(p/32): 0.553x the HMMA of rectangular.
// B_frag = bf16 tile0 (W[p,q-row]) + bf16 tile1 (W[q-row,p] transposed gather),
// combined via ldmatrix x2 + add.bf16x2. Diagonal-window masking by redirecting
// cp.async source to a zero page. Load balance: p-block permutation pairs heavy
// (z'=0: 336 stages) with light (z'=17: 32) on the same SM.
#define BPITCH  272u                        // bytes per k-row (128 bf16 + 16B pad)
#define BTILE   8704u                       // 32 * 272 (one tile)
#define BSTAGE  17408u                      // tile0 + tile1
#define GOFF_ZP 0u                          // [128][25] f32 = 12800
#define GOFF_B  12800u                      // 4 x 17408
#define GSMEM   82432u

__global__ __launch_bounds__(256, 2) void inter_gemm_kernel() {
    extern __shared__ char smem[];
    const uint32_t sb = smem_u32(smem);
    float* zp_s = (float*)(smem + GOFF_ZP);   // row pitch 25 floats

    const int tid = threadIdx.x;
    const int warp = tid >> 5, lane = tid & 31;
    const int g = lane >> 2, c = lane & 3;
    const int m0 = blockIdx.x * 128;
    const int n0 = blockIdx.y * 128;
    const int bz = blockIdx.z;
    const int pz = (bz <= 8) ? 2 * bz : (35 - 2 * bz);   // heavy/light pairing perm
    const int p0 = 24 * pz;
    const int lo = p0 >> 5;
    const int hi = (p0 + 23) >> 5;
    const int cLow = (lo == hi) ? 24 : (32 * hi - p0);   // actives in boundary window
    const int wm0 = (warp >> 2) * 64, wn0 = (warp & 3) * 32;

    // total stages for this CTA
    int S = 0;
    for (int w = lo; w < 14; w++) S += (w >= hi) ? 24 : cLow;

    // ---- load zp [128][24] (index j -> p = p0 + j) ----
    for (int i = tid; i < 128 * 24; i += 256) {
        int b = i / 24, j = i - b * 24;
        zp_s[b * 25 + j] = g_z[(size_t)(m0 + b) * 448 + p0 + j];
    }
    __syncthreads();

    // ---- cp.async params: thread -> (k row, 32B n-chunk) ----
    const int brow = tid >> 3;                // k row 0..31
    const int bco = (tid & 7) * 16;           // bf16 element offset (16 elems = 32B)
    const uint32_t bdst = sb + GOFF_B + (uint32_t)(brow * BPITCH + bco * 2);
    const void* zsrc = (const void*)g_zero4;

#define CNT(W) (((W) >= hi) ? 24 : cLow)
#define ADV(W, J) do { if (++(J) == CNT(W)) { (J) = 0; (W)++; } } while (0)

#define ISSUE_STAGE(T, WI, JI) do {                                            \
        int p_ = p0 + (JI);                                                    \
        int q_ = 32 * (WI) + brow;                                             \
        int dg_ = ((p_ >> 5) == (WI));                                         \
        int nz_ = p_ & 31;                                                     \
        const void* s0_ = (q_ > 431 || (dg_ && brow < nz_)) ? zsrc :           \
            (const void*)(g_w0c + ((size_t)p_ * 432 + q_) * 512 + n0 + bco);   \
        const void* s1_ = (q_ > 431 || (dg_ && brow <= nz_)) ? zsrc :          \
            (const void*)(g_w0c + ((size_t)q_ * 432 + p_) * 512 + n0 + bco);   \
        uint32_t d_ = bdst + ((T) & 3) * BSTAGE;                               \
        cpasync32(d_, s0_);                                                    \
        cpasync32(d_ + BTILE, s1_);                                            \
    } while (0)

    int wI = lo, jI = 0;
    ISSUE_STAGE(0, wI, jI); CP_COMMIT(); ADV(wI, jI);
    ISSUE_STAGE(1, wI, jI); CP_COMMIT(); ADV(wI, jI);
    ISSUE_STAGE(2, wI, jI); CP_COMMIT(); ADV(wI, jI);

    // ---- zq register cache: 8 rows x 4 k-pair slots (k = 2c + 8j) ----
    uint32_t zq_c[8][4];
#define LOAD_ZQ(W) do {                                                        \
        _Pragma("unroll")                                                      \
        for (int rr_ = 0; rr_ < 8; rr_++) {                                    \
            int row_ = m0 + wm0 + (rr_ >> 1) * 16 + ((rr_ & 1) << 3) + g;      \
            const float* zr_ = g_z + (size_t)row_ * 448 + (W) * 32 + 2 * c;    \
            _Pragma("unroll")                                                  \
            for (int j_ = 0; j_ < 4; j_++) {                                   \
                float2 v_ = *(const float2*)(zr_ + 8 * j_);                    \
                zq_c[rr_][j_] = pack_bf16(v_.x, v_.y);                         \
            }                                                                  \
        }                                                                      \
    } while (0)

    float acc[4][4][4];
    #pragma unroll
    for (int mi = 0; mi < 4; mi++)
        #pragma unroll
        for (int nj = 0; nj < 4; nj++)
            #pragma unroll
            for (int k = 0; k < 4; k++) acc[mi][nj][k] = 0.f;

    const uint32_t b_lrow = (uint32_t)((lane & 15) * BPITCH + ((lane >> 4) & 1) * 16);

    int wC = lo, jC = 0;
    for (int t = 0; t < S; t++) {
        CP_WAIT2();
        __syncthreads();                       // stage t visible; buffer (t+3)&3 free
        if (t + 3 < S) { ISSUE_STAGE(t + 3, wI, jI); ADV(wI, jI); }
        CP_COMMIT();

        if (jC == 0) LOAD_ZQ(wC);              // new window: refresh zq cache

        // zp broadcast for this stage's p
        uint32_t zp2[8];
        #pragma unroll
        for (int rr = 0; rr < 8; rr++) {
            int row = wm0 + (rr >> 1) * 16 + ((rr & 1) << 3) + g;
            float v = zp_s[row * 25 + jC];
            zp2[rr] = pack_bf16(v, v);
        }

        const uint32_t S0 = sb + GOFF_B + (uint32_t)((t & 3) * BSTAGE);

        #pragma unroll
        for (int ks = 0; ks < 2; ks++) {
            uint32_t bfr[2][4];
            #pragma unroll
            for (int njp = 0; njp < 2; njp++) {
                uint32_t addr = S0 + (uint32_t)(ks * 16 * BPITCH + (wn0 + njp * 16) * 2) + b_lrow;
                uint32_t t0[4], t1[4];
                LDSM4T(t0[0], t0[1], t0[2], t0[3], addr);
                LDSM4T(t1[0], t1[1], t1[2], t1[3], addr + BTILE);
                #pragma unroll
                for (int r = 0; r < 4; r++) bfr[njp][r] = hadd2(t0[r], t1[r]);
            }

            #pragma unroll
            for (int mi = 0; mi < 4; mi++) {
                uint32_t a0 = hmul2(zp2[2 * mi],     zq_c[2 * mi][ks * 2]);
                uint32_t a1 = hmul2(zp2[2 * mi + 1], zq_c[2 * mi + 1][ks * 2]);
                uint32_t a2 = hmul2(zp2[2 * mi],     zq_c[2 * mi][ks * 2 + 1]);
                uint32_t a3 = hmul2(zp2[2 * mi + 1], zq_c[2 * mi + 1][ks * 2 + 1]);
                #pragma unroll
                for (int nj = 0; nj < 4; nj++) {
                    uint32_t b0 = bfr[nj >> 1][(nj & 1) * 2];
                    uint32_t b1 = bfr[nj >> 1][(nj & 1) * 2 + 1];
                    asm volatile(
                        "mma.sync.aligned.m16n8k16.row.col.f32.bf16.bf16.f32 "
                        "{%0,%1,%2,%3},{%4,%5,%6,%7},{%8,%9},{%0,%1,%2,%3};"
                        : "+f"(acc[mi][nj][0]), "+f"(acc[mi][nj][1]),
                          "+f"(acc[mi][nj][2]), "+f"(acc[mi][nj][3])
                        : "r"(a0), "r"(a1), "r"(a2), "r"(a3),
                          "r"(b0), "r"(b1));
                }
            }
        }

        ADV(wC, jC);
    }

    // epilogue: write split partials
    #pragma unroll
    for (int mi = 0; mi < 4; mi++)
        #pragma unroll
        for (int nj = 0; nj < 4; nj++) {
            int row = m0 + wm0 + 16 * mi + g;
            int col = n0 + wn0 + 8 * nj + 2 * c;
            float* d0 = g_part + ((size_t)bz * 512 + row) * 512 + col;
            float* d1 = g_part + ((size_t)bz * 512 + row + 8) * 512 + col;
            *(float2*)d0 = make_float2(acc[mi][nj][0], acc[mi][nj][1]);
            *(float2*)d1 = make_float2(acc[mi][nj][2], acc[mi][nj][3]);
        }
}
#undef ISSUE_STAGE
#undef LOAD_ZQ
#undef CNT
#undef ADV

// ---------------- kernel 4: reduce split-K partials + bias + relu ----------
__global__ void reduce_relu_kernel(const float* __restrict__ pb0) {
    int b = blockIdx.x;
    for (int j = threadIdx.x; j < 512; j += 256) {
        float s = pb0[j];
        #pragma unroll
        for (int sp = 0; sp < 18; sp++)
            s += g_part[((size_t)sp * 512 + b) * 512 + j];
        g_h1[(size_t)b * 512 + j] = fmaxf(s, 0.f);
    }
}

// ---------------- kernel 5: prediction MLP + sigmoid -----------------------
__global__ void pred_kernel(const float* __restrict__ pw1, const float* __restrict__ pb1,
                            const float* __restrict__ pw2, const float* __restrict__ pb2,
                            float* __restrict__ out) {
    __shared__ float h1s[4][512];
    __shared__ float h2s[4][256];
    __shared__ float red[4][8];
    const int r0 = blockIdx.x * 4;
    const int tid = threadIdx.x;

    for (int i = tid; i < 2048; i += 256)
        h1s[i >> 9][i & 511] = g_h1[(size_t)(r0 + (i >> 9)) * 512 + (i & 511)];
    __syncthreads();

    {
        float a[4];
        float b = pb1[tid];
        #pragma unroll
        for (int r = 0; r < 4; r++) a[r] = b;
        #pragma unroll 16
        for (int i = 0; i < 512; i++) {
            float w = pw1[i * 256 + tid];
            #pragma unroll
            for (int r = 0; r < 4; r++) a[r] += h1s[r][i] * w;
        }
        #pragma unroll
        for (int r = 0; r < 4; r++) h2s[r][tid] = fmaxf(a[r], 0.f);
    }
    __syncthreads();

    float w2 = pw2[tid];
    int lane = tid & 31, wp = tid >> 5;
    #pragma unroll
    for (int r = 0; r < 4; r++) {
        float v = h2s[r][tid] * w2;
        #pragma unroll
        for (int o = 16; o; o >>= 1) v += __shfl_xor_sync(0xffffffffu, v, o);
        if (lane == 0) red[r][wp] = v;
    }
    __syncthreads();
    if (tid < 4) {
        float s = pb2[0];
        #pragma unroll
        for (int w = 0; w < 8; w++) s += red[tid][w];
        out[r0 + tid] = 1.f / (1.f + expf(-s));
    }
}

// ---------------- launch ----------------------------------------------------
extern "C" void kernel_launch(void* const* d_in, const int* in_sizes, int n_in,
                              void* d_out, int out_size) {
    const float* x   = (const float*)d_in[0];
    const void*  sp  = d_in[1];
    const float* emb = (const float*)d_in[2];
    const float* dw0 = (const float*)d_in[3];
    const float* db0 = (const float*)d_in[4];
    const float* dw1 = (const float*)d_in[5];
    const float* db1 = (const float*)d_in[6];
    const float* dw2 = (const float*)d_in[7];
    const float* db2 = (const float*)d_in[8];
    const float* dw3 = (const float*)d_in[9];
    const float* db3 = (const float*)d_in[10];
    const float* pw0 = (const float*)d_in[11];
    const float* pb0 = (const float*)d_in[12];
    const float* pw1 = (const float*)d_in[13];
    const float* pb1 = (const float*)d_in[14];
    const float* pw2 = (const float*)d_in[15];
    const float* pb2 = (const float*)d_in[16];
    float* out = (float*)d_out;

    cudaFuncSetAttribute(inter_gemm_kernel,
                         cudaFuncAttributeMaxDynamicSharedMemorySize, (int)GSMEM);

    convert_w0_kernel<<<23328, 256>>>(pw0);   // 186624*512 / 16 / 256
    dense_mlp_kernel<<<128, 256>>>(x, dw0, db0, dw1, db1, dw2, db2, dw3, db3);
    embed_kernel<<<52, 256>>>(sp, emb);
    inter_gemm_kernel<<<dim3(4, 4, 18), 256, GSMEM>>>();
    reduce_relu_kernel<<<512, 256>>>(pb0);
    pred_kernel<<<128, 256>>>(pw1, pb1, pw2, pb2, out);
}

// round 15
// speedup vs baseline: 3.6395x; 3.6395x over previous
#include <cuda_runtime.h>
#include <cuda_bf16.h>
#include <math.h>
#include <stdint.h>

// ---------------- scratch (device globals; no allocs allowed) ----------------
__device__ float g_z[512 * 448];            // z padded to 448 cols (cols 432..447 = 0)
__device__ float g_part[18 * 512 * 512];    // split-K partials
__device__ float g_h1[512 * 512];           // relu(inter@pw0+pb0)
// symmetric-folded W0, window-major packed stream:
// stage s=(w,p), p in [0,32*(w+1)), base 16*w*(w+1); 3360 stages x [32k][512n] bf16
__device__ __nv_bfloat16 g_w0s[(size_t)3360 * 16384];

// pack two fp32 -> bf16x2 (lo -> low half)
__device__ __forceinline__ uint32_t pack_bf16(float lo, float hi) {
    uint32_t r;
    asm("cvt.rn.bf16x2.f32 %0, %1, %2;" : "=r"(r) : "f"(hi), "f"(lo));
    return r;
}
__device__ __forceinline__ uint32_t hmul2(uint32_t a, uint32_t b) {
    uint32_t r;
    asm("mul.rn.bf16x2 %0, %1, %2;" : "=r"(r) : "r"(a), "r"(b));
    return r;
}
__device__ __forceinline__ uint32_t smem_u32(const void* p) {
    uint32_t a;
    asm("{ .reg .u64 t; cvta.to.shared.u64 t, %1; cvt.u32.u64 %0, t; }" : "=r"(a) : "l"(p));
    return a;
}
#define LDSM4T(R0, R1, R2, R3, ADDR)                                           \
    asm volatile("ldmatrix.sync.aligned.m8n8.x4.trans.shared.b16 {%0,%1,%2,%3}, [%4];" \
                 : "=r"(R0), "=r"(R1), "=r"(R2), "=r"(R3) : "r"(ADDR))
__device__ __forceinline__ void cpasync32(uint32_t dst, const void* src) {
    asm volatile(
        "cp.async.cg.shared.global [%0], [%1], 16;\n\t"
        "cp.async.cg.shared.global [%2], [%3], 16;"
        :: "r"(dst), "l"(src), "r"(dst + 16), "l"((const char*)src + 16) : "memory");
}
#define CP_COMMIT() asm volatile("cp.async.commit_group;" ::: "memory")
#define CP_WAIT2()  asm volatile("cp.async.wait_group 2;" ::: "memory")

// ---------------- kernel 0: fold W0 -> symmetric packed bf16 stream ---------
// block (pb, w): 16 p-values of window w. Each W element read EXACTLY once:
// row side W[p, 32w..+32] contiguous; transpose side W[q, p] 2KB chunks.
__global__ void fold_w0_kernel(const float* __restrict__ W0) {
    const int pb = blockIdx.x, w = blockIdx.y;
    const int p0 = pb * 16;
    if (p0 >= 32 * (w + 1)) return;            // outside this window's p-range
    const int tid = threadIdx.x;
    const int warp = tid >> 5, lane = tid & 31;
    const int n = lane * 16;                    // 16 consecutive n per lane

    const size_t sbase = (size_t)16 * w * (w + 1);

    for (int r = warp; r < 512; r += 8) {       // r = i*32 + k
        const int i = r >> 5, k = r & 31;
        const int p = p0 + i;
        if (p >= 32 * (w + 1)) break;           // i nondecreasing -> safe
        const int q = 32 * w + k;
        __nv_bfloat16* dst = g_w0s + (sbase + p) * 16384 + (size_t)k * 512 + n;

        const bool zero = (p >= 432) || (q > 431) || (((p >> 5) == w) && q < p);
        if (zero) {
            uint4 z = make_uint4(0, 0, 0, 0);
            __stcs((uint4*)dst, z);
            __stcs((uint4*)(dst + 8), z);
        } else if (q == p) {                    // diagonal: W[p,p] once
            const float* s0 = W0 + ((size_t)p * 432 + q) * 512 + n;
            float4 a = __ldcs((const float4*)s0);
            float4 b = __ldcs((const float4*)(s0 + 4));
            float4 c = __ldcs((const float4*)(s0 + 8));
            float4 d = __ldcs((const float4*)(s0 + 12));
            uint4 o0 = make_uint4(pack_bf16(a.x, a.y), pack_bf16(a.z, a.w),
                                  pack_bf16(b.x, b.y), pack_bf16(b.z, b.w));
            uint4 o1 = make_uint4(pack_bf16(c.x, c.y), pack_bf16(c.z, c.w),
                                  pack_bf16(d.x, d.y), pack_bf16(d.z, d.w));
            __stcs((uint4*)dst, o0);
            __stcs((uint4*)(dst + 8), o1);
        } else {                                // off-diag: W[p,q] + W[q,p]
            const float* s0 = W0 + ((size_t)p * 432 + q) * 512 + n;
            const float* s1 = W0 + ((size_t)q * 432 + p) * 512 + n;
            float4 a = __ldcs((const float4*)s0);
            float4 b = __ldcs((const float4*)(s0 + 4));
            float4 c = __ldcs((const float4*)(s0 + 8));
            float4 d = __ldcs((const float4*)(s0 + 12));
            float4 e = __ldcs((const float4*)s1);
            float4 f = __ldcs((const float4*)(s1 + 4));
            float4 gg = __ldcs((const float4*)(s1 + 8));
            float4 h = __ldcs((const float4*)(s1 + 12));
            uint4 o0 = make_uint4(pack_bf16(a.x + e.x, a.y + e.y),
                                  pack_bf16(a.z + e.z, a.w + e.w),
                                  pack_bf16(b.x + f.x, b.y + f.y),
                                  pack_bf16(b.z + f.z, b.w + f.w));
            uint4 o1 = make_uint4(pack_bf16(c.x + gg.x, c.y + gg.y),
                                  pack_bf16(c.z + gg.z, c.w + gg.w),
                                  pack_bf16(d.x + h.x, d.y + h.y),
                                  pack_bf16(d.z + h.z, d.w + h.w));
            __stcs((uint4*)dst, o0);
            __stcs((uint4*)(dst + 8), o1);
        }
    }
}

// ---------------- kernel 1: dense MLP (4 batch rows / block) ----------------
__global__ void dense_mlp_kernel(const float* __restrict__ x,
                                 const float* __restrict__ dw0, const float* __restrict__ db0,
                                 const float* __restrict__ dw1, const float* __restrict__ db1,
                                 const float* __restrict__ dw2, const float* __restrict__ db2,
                                 const float* __restrict__ dw3, const float* __restrict__ db3) {
    __shared__ float xs[4][13];
    __shared__ float h0[4][512];
    __shared__ float h1[4][256];
    __shared__ float h2[4][64];
    const int r0 = blockIdx.x * 4;
    const int tid = threadIdx.x;

    if (tid < 52) xs[tid / 13][tid % 13] = x[(r0 + tid / 13) * 13 + tid % 13];
    __syncthreads();

    #pragma unroll
    for (int jj = 0; jj < 2; jj++) {
        int j = tid + jj * 256;
        float a[4];
        float b = db0[j];
        #pragma unroll
        for (int r = 0; r < 4; r++) a[r] = b;
        #pragma unroll
        for (int i = 0; i < 13; i++) {
            float w = dw0[i * 512 + j];
            #pragma unroll
            for (int r = 0; r < 4; r++) a[r] += xs[r][i] * w;
        }
        #pragma unroll
        for (int r = 0; r < 4; r++) h0[r][j] = fmaxf(a[r], 0.f);
    }
    __syncthreads();

    {
        float a[4];
        float b = db1[tid];
        #pragma unroll
        for (int r = 0; r < 4; r++) a[r] = b;
        #pragma unroll 8
        for (int i = 0; i < 512; i++) {
            float w = dw1[i * 256 + tid];
            #pragma unroll
            for (int r = 0; r < 4; r++) a[r] += h0[r][i] * w;
        }
        #pragma unroll
        for (int r = 0; r < 4; r++) h1[r][tid] = fmaxf(a[r], 0.f);
    }
    __syncthreads();

    if (tid < 64) {
        float a[4];
        float b = db2[tid];
        #pragma unroll
        for (int r = 0; r < 4; r++) a[r] = b;
        #pragma unroll 8
        for (int i = 0; i < 256; i++) {
            float w = dw2[i * 64 + tid];
            #pragma unroll
            for (int r = 0; r < 4; r++) a[r] += h1[r][i] * w;
        }
        #pragma unroll
        for (int r = 0; r < 4; r++) h2[r][tid] = fmaxf(a[r], 0.f);
    }
    __syncthreads();

    if (tid < 16) {
        float a[4];
        float b = db3[tid];
        #pragma unroll
        for (int r = 0; r < 4; r++) a[r] = b;
        #pragma unroll
        for (int i = 0; i < 64; i++) {
            float w = dw3[i * 16 + tid];
            #pragma unroll
            for (int r = 0; r < 4; r++) a[r] += h2[r][i] * w;
        }
        #pragma unroll
        for (int r = 0; r < 4; r++) g_z[(size_t)(r0 + r) * 448 + tid] = a[r];
    }
    if (tid >= 64 && tid < 128) {
        int u = tid - 64;
        g_z[(size_t)(r0 + u / 16) * 448 + 432 + (u % 16)] = 0.f;
    }
}

// ---------------- kernel 2: embedding gather -> z[:,16:432] ----------------
__global__ void embed_kernel(const void* __restrict__ sp, const float* __restrict__ emb) {
    int t = blockIdx.x * blockDim.x + threadIdx.x;
    if (t >= 512 * 26) return;
    const int* si = (const int*)sp;
    bool is64 = (si[1] == 0 && si[3] == 0 && si[5] == 0);
    long long v = is64 ? ((const long long*)sp)[t] : (long long)si[t];
    int id = (int)((v + 1) % 100000);
    int b = t / 26, f = t - b * 26;
    const float4* src = (const float4*)(emb + ((size_t)f * 100000 + id) * 16);
    float4* dst = (float4*)(g_z + (size_t)b * 448 + 16 + f * 16);
    dst[0] = src[0]; dst[1] = src[1]; dst[2] = src[2]; dst[3] = src[3];
}

// ---------------- kernel 3: symmetric interaction GEMM ----------------------
// C[b,n] = sum_s A_s @ Bfold_s over the linear packed stream (0.553x HMMA).
// CTA: 128m x 128n; 18 splits (6x188 + 12x186 stages) -> 288 CTAs = 2/SM.
// Issue side is PURELY LINEAR in s (no tables/gathers). Consume side tracks
// (w,p) with two registers; zq register cache per window; zp via quad LDG.
#define BPITCH  272u                        // bytes per staged k-row
#define BTILE   8704u                       // 32 * 272 (one stage)
#define BSTAGE  17408u                      // slot = 2 stages
#define GSMEM   69632u                      // 4-slot ring

__global__ __launch_bounds__(256, 2) void inter_gemm_kernel() {
    extern __shared__ char smem[];
    const uint32_t sb = smem_u32(smem);

    const int tid = threadIdx.x;
    const int warp = tid >> 5, lane = tid & 31;
    const int g = lane >> 2, c = lane & 3;
    const int m0 = blockIdx.x * 128;
    const int n0 = blockIdx.y * 128;
    const int bz = blockIdx.z;
    const int wm0 = (warp >> 2) * 64, wn0 = (warp & 3) * 32;

    const int sA = (bz < 6) ? 188 * bz : 1128 + 186 * (bz - 6);
    const int cnt = (bz < 6) ? 188 : 186;
    const int nslots = cnt >> 1;

    // ---- cp.async params: thread -> (k row, 32B n-chunk) ----
    const int brow = tid >> 3;
    const int bco = (tid & 7) * 16;            // bf16 elems (32B)
    const uint32_t bdst = sb + (uint32_t)(brow * BPITCH + bco * 2);

#define ISSUE_SLOT(T) do {                                                     \
        size_t s_ = (size_t)(sA + 2 * (T));                                    \
        uint32_t d_ = bdst + ((T) & 3) * BSTAGE;                               \
        cpasync32(d_,         g_w0s + s_ * 16384 + brow * 512 + n0 + bco);     \
        cpasync32(d_ + BTILE, g_w0s + (s_ + 1) * 16384 + brow * 512 + n0 + bco); \
    } while (0)

    ISSUE_SLOT(0); CP_COMMIT();
    ISSUE_SLOT(1); CP_COMMIT();
    ISSUE_SLOT(2); CP_COMMIT();

    // ---- consume-side (w, p) tracking ----
    int w = 0;
    while (16 * (w + 1) * (w + 2) <= sA) w++;
    int p = sA - 16 * w * (w + 1);
    int wnext = 16 * (w + 1) * (w + 2);

    // ---- zq register cache: 8 rows x 4 k-pair slots (k = 2c + 8j) ----
    uint32_t zq_c[8][4];
#define LOAD_ZQ(W) do {                                                        \
        _Pragma("unroll")                                                      \
        for (int rr_ = 0; rr_ < 8; rr_++) {                                    \
            int row_ = m0 + wm0 + (rr_ >> 1) * 16 + ((rr_ & 1) << 3) + g;      \
            const float* zr_ = g_z + (size_t)row_ * 448 + (W) * 32 + 2 * c;    \
            _Pragma("unroll")                                                  \
            for (int j_ = 0; j_ < 4; j_++) {                                   \
                float2 v_ = *(const float2*)(zr_ + 8 * j_);                    \
                zq_c[rr_][j_] = pack_bf16(v_.x, v_.y);                         \
            }                                                                  \
        }                                                                      \
    } while (0)

    LOAD_ZQ(w);

    float acc[4][4][4];
    #pragma unroll
    for (int mi = 0; mi < 4; mi++)
        #pragma unroll
        for (int nj = 0; nj < 4; nj++)
            #pragma unroll
            for (int k = 0; k < 4; k++) acc[mi][nj][k] = 0.f;

    const uint32_t b_lrow = (uint32_t)((lane & 15) * BPITCH + ((lane >> 4) & 1) * 16);
    int scons = sA;

    for (int t = 0; t < nslots; t++) {
        CP_WAIT2();
        __syncthreads();                       // slot t visible; buffer (t+3)&3 free
        if (t + 3 < nslots) ISSUE_SLOT(t + 3);
        CP_COMMIT();

        const uint32_t S0 = sb + (uint32_t)((t & 3) * BSTAGE);

        #pragma unroll
        for (int hh = 0; hh < 2; hh++) {
            if (scons == wnext) {              // window boundary (rare)
                w++; wnext += 32 * (w + 1); p = 0;
                LOAD_ZQ(w);
            }
            // zp column p for this warp's 8 m-rows (quad-broadcast LDG, L2-hot)
            float zpv[8];
            #pragma unroll
            for (int rr = 0; rr < 8; rr++) {
                int row = m0 + wm0 + (rr >> 1) * 16 + ((rr & 1) << 3) + g;
                zpv[rr] = __ldg(g_z + (size_t)row * 448 + p);
            }
            const uint32_t B_base = S0 + hh * BTILE;

            #pragma unroll
            for (int ks = 0; ks < 2; ks++) {
                uint32_t bfr[2][4];
                #pragma unroll
                for (int njp = 0; njp < 2; njp++)
                    LDSM4T(bfr[njp][0], bfr[njp][1], bfr[njp][2], bfr[njp][3],
                           B_base + (uint32_t)(ks * 16 * BPITCH + (wn0 + njp * 16) * 2) + b_lrow);

                #pragma unroll
                for (int mi = 0; mi < 4; mi++) {
                    uint32_t zp2a = pack_bf16(zpv[2 * mi], zpv[2 * mi]);
                    uint32_t zp2b = pack_bf16(zpv[2 * mi + 1], zpv[2 * mi + 1]);
                    uint32_t a0 = hmul2(zp2a, zq_c[2 * mi][ks * 2]);
                    uint32_t a1 = hmul2(zp2b, zq_c[2 * mi + 1][ks * 2]);
                    uint32_t a2 = hmul2(zp2a, zq_c[2 * mi][ks * 2 + 1]);
                    uint32_t a3 = hmul2(zp2b, zq_c[2 * mi + 1][ks * 2 + 1]);
                    #pragma unroll
                    for (int nj = 0; nj < 4; nj++) {
                        uint32_t b0 = bfr[nj >> 1][(nj & 1) * 2];
                        uint32_t b1 = bfr[nj >> 1][(nj & 1) * 2 + 1];
                        asm volatile(
                            "mma.sync.aligned.m16n8k16.row.col.f32.bf16.bf16.f32 "
                            "{%0,%1,%2,%3},{%4,%5,%6,%7},{%8,%9},{%0,%1,%2,%3};"
                            : "+f"(acc[mi][nj][0]), "+f"(acc[mi][nj][1]),
                              "+f"(acc[mi][nj][2]), "+f"(acc[mi][nj][3])
                            : "r"(a0), "r"(a1), "r"(a2), "r"(a3),
                              "r"(b0), "r"(b1));
                    }
                }
            }
            p++; scons++;
        }
    }

    // epilogue: write split partials
    #pragma unroll
    for (int mi = 0; mi < 4; mi++)
        #pragma unroll
        for (int nj = 0; nj < 4; nj++) {
            int row = m0 + wm0 + 16 * mi + g;
            int col = n0 + wn0 + 8 * nj + 2 * c;
            float* d0 = g_part + ((size_t)bz * 512 + row) * 512 + col;
            float* d1 = g_part + ((size_t)bz * 512 + row + 8) * 512 + col;
            *(float2*)d0 = make_float2(acc[mi][nj][0], acc[mi][nj][1]);
            *(float2*)d1 = make_float2(acc[mi][nj][2], acc[mi][nj][3]);
        }
}
#undef ISSUE_SLOT
#undef LOAD_ZQ

// ---------------- kernel 4: reduce split-K partials + bias + relu ----------
__global__ void reduce_relu_kernel(const float* __restrict__ pb0) {
    int b = blockIdx.x;
    for (int j = threadIdx.x; j < 512; j += 256) {
        float s = pb0[j];
        #pragma unroll
        for (int sp = 0; sp < 18; sp++)
            s += g_part[((size_t)sp * 512 + b) * 512 + j];
        g_h1[(size_t)b * 512 + j] = fmaxf(s, 0.f);
    }
}

// ---------------- kernel 5: prediction MLP + sigmoid -----------------------
__global__ void pred_kernel(const float* __restrict__ pw1, const float* __restrict__ pb1,
                            const float* __restrict__ pw2, const float* __restrict__ pb2,
                            float* __restrict__ out) {
    __shared__ float h1s[4][512];
    __shared__ float h2s[4][256];
    __shared__ float red[4][8];
    const int r0 = blockIdx.x * 4;
    const int tid = threadIdx.x;

    for (int i = tid; i < 2048; i += 256)
        h1s[i >> 9][i & 511] = g_h1[(size_t)(r0 + (i >> 9)) * 512 + (i & 511)];
    __syncthreads();

    {
        float a[4];
        float b = pb1[tid];
        #pragma unroll
        for (int r = 0; r < 4; r++) a[r] = b;
        #pragma unroll 8
        for (int i = 0; i < 512; i++) {
            float w = pw1[i * 256 + tid];
            #pragma unroll
            for (int r = 0; r < 4; r++) a[r] += h1s[r][i] * w;
        }
        #pragma unroll
        for (int r = 0; r < 4; r++) h2s[r][tid] = fmaxf(a[r], 0.f);
    }
    __syncthreads();

    float w2 = pw2[tid];
    int lane = tid & 31, wp = tid >> 5;
    #pragma unroll
    for (int r = 0; r < 4; r++) {
        float v = h2s[r][tid] * w2;
        #pragma unroll
        for (int o = 16; o; o >>= 1) v += __shfl_xor_sync(0xffffffffu, v, o);
        if (lane == 0) red[r][wp] = v;
    }
    __syncthreads();
    if (tid < 4) {
        float s = pb2[0];
        #pragma unroll
        for (int w = 0; w < 8; w++) s += red[tid][w];
        out[r0 + tid] = 1.f / (1.f + expf(-s));
    }
}

// ---------------- launch ----------------------------------------------------
extern "C" void kernel_launch(void* const* d_in, const int* in_sizes, int n_in,
                              void* d_out, int out_size) {
    const float* x   = (const float*)d_in[0];
    const void*  sp  = d_in[1];
    const float* emb = (const float*)d_in[2];
    const float* dw0 = (const float*)d_in[3];
    const float* db0 = (const float*)d_in[4];
    const float* dw1 = (const float*)d_in[5];
    const float* db1 = (const float*)d_in[6];
    const float* dw2 = (const float*)d_in[7];
    const float* db2 = (const float*)d_in[8];
    const float* dw3 = (const float*)d_in[9];
    const float* db3 = (const float*)d_in[10];
    const float* pw0 = (const float*)d_in[11];
    const float* pb0 = (const float*)d_in[12];
    const float* pw1 = (const float*)d_in[13];
    const float* pb1 = (const float*)d_in[14];
    const float* pw2 = (const float*)d_in[15];
    const float* pb2 = (const float*)d_in[16];
    float* out = (float*)d_out;

    cudaFuncSetAttribute(inter_gemm_kernel,
                         cudaFuncAttributeMaxDynamicSharedMemorySize, (int)GSMEM);

    fold_w0_kernel<<<dim3(28, 14), 256>>>(pw0);
    dense_mlp_kernel<<<128, 256>>>(x, dw0, db0, dw1, db1, dw2, db2, dw3, db3);
    embed_kernel<<<52, 256>>>(sp, emb);
    inter_gemm_kernel<<<dim3(4, 4, 18), 256, GSMEM>>>();
    reduce_relu_kernel<<<512, 256>>>(pb0);
    pred_kernel<<<128, 256>>>(pw1, pb1, pw2, pb2, out);
}

// round 16
// speedup vs baseline: 3.7374x; 1.0269x over previous
#include <cuda_runtime.h>
#include <cuda_bf16.h>
#include <math.h>
#include <stdint.h>

// ---------------- scratch (device globals; no allocs allowed) ----------------
__device__ float g_z[512 * 448];            // z padded to 448 cols (cols 432..447 = 0)
__device__ float g_part[18 * 512 * 512];    // split-K partials
__device__ float g_h1[512 * 512];           // relu(inter@pw0+pb0)
// symmetric-folded W0, window-major packed stream:
// stage s=(w,p), p in [0,32*(w+1)), base 16*w*(w+1); 3360 stages x [32k][512n] bf16
__device__ __nv_bfloat16 g_w0s[(size_t)3360 * 16384];

// pack two fp32 -> bf16x2 (lo -> low half)
__device__ __forceinline__ uint32_t pack_bf16(float lo, float hi) {
    uint32_t r;
    asm("cvt.rn.bf16x2.f32 %0, %1, %2;" : "=r"(r) : "f"(hi), "f"(lo));
    return r;
}
__device__ __forceinline__ uint32_t hmul2(uint32_t a, uint32_t b) {
    uint32_t r;
    asm("mul.rn.bf16x2 %0, %1, %2;" : "=r"(r) : "r"(a), "r"(b));
    return r;
}
__device__ __forceinline__ uint32_t smem_u32(const void* p) {
    uint32_t a;
    asm("{ .reg .u64 t; cvta.to.shared.u64 t, %1; cvt.u32.u64 %0, t; }" : "=r"(a) : "l"(p));
    return a;
}
#define LDSM4T(R0, R1, R2, R3, ADDR)                                           \
    asm volatile("ldmatrix.sync.aligned.m8n8.x4.trans.shared.b16 {%0,%1,%2,%3}, [%4];" \
                 : "=r"(R0), "=r"(R1), "=r"(R2), "=r"(R3) : "r"(ADDR))
__device__ __forceinline__ void cpasync32(uint32_t dst, const void* src) {
    asm volatile(
        "cp.async.cg.shared.global [%0], [%1], 16;\n\t"
        "cp.async.cg.shared.global [%2], [%3], 16;"
        :: "r"(dst), "l"(src), "r"(dst + 16), "l"((const char*)src + 16) : "memory");
}
#define CP_COMMIT() asm volatile("cp.async.commit_group;" ::: "memory")
#define CP_WAIT2()  asm volatile("cp.async.wait_group 2;" ::: "memory")

// ---------------- kernel 0: fold W0 -> symmetric packed bf16 stream ---------
// block (pb, w): FOUR p-values of window w (840 active CTAs -> latency hidden).
// Each W element read EXACTLY once: row side contiguous, transpose side 2KB chunks.
__global__ void fold_w0_kernel(const float* __restrict__ W0) {
    const int pb = blockIdx.x, w = blockIdx.y;
    const int p0 = pb * 4;
    if (p0 >= 32 * (w + 1)) return;            // outside this window's p-range
    const int tid = threadIdx.x;
    const int warp = tid >> 5, lane = tid & 31;
    const int n = lane * 16;                    // 16 consecutive n per lane

    const size_t sbase = (size_t)16 * w * (w + 1);

    for (int r = warp; r < 128; r += 8) {       // r = i*32 + k, i in 0..3
        const int i = r >> 5, k = r & 31;
        const int p = p0 + i;
        if (p >= 32 * (w + 1)) break;           // i nondecreasing -> safe
        const int q = 32 * w + k;
        __nv_bfloat16* dst = g_w0s + (sbase + p) * 16384 + (size_t)k * 512 + n;

        const bool zero = (p >= 432) || (q > 431) || (((p >> 5) == w) && q < p);
        if (zero) {
            uint4 z = make_uint4(0, 0, 0, 0);
            __stcs((uint4*)dst, z);
            __stcs((uint4*)(dst + 8), z);
        } else if (q == p) {                    // diagonal: W[p,p] once
            const float* s0 = W0 + ((size_t)p * 432 + q) * 512 + n;
            float4 a = __ldcs((const float4*)s0);
            float4 b = __ldcs((const float4*)(s0 + 4));
            float4 c = __ldcs((const float4*)(s0 + 8));
            float4 d = __ldcs((const float4*)(s0 + 12));
            uint4 o0 = make_uint4(pack_bf16(a.x, a.y), pack_bf16(a.z, a.w),
                                  pack_bf16(b.x, b.y), pack_bf16(b.z, b.w));
            uint4 o1 = make_uint4(pack_bf16(c.x, c.y), pack_bf16(c.z, c.w),
                                  pack_bf16(d.x, d.y), pack_bf16(d.z, d.w));
            __stcs((uint4*)dst, o0);
            __stcs((uint4*)(dst + 8), o1);
        } else {                                // off-diag: W[p,q] + W[q,p]
            const float* s0 = W0 + ((size_t)p * 432 + q) * 512 + n;
            const float* s1 = W0 + ((size_t)q * 432 + p) * 512 + n;
            float4 a = __ldcs((const float4*)s0);
            float4 b = __ldcs((const float4*)(s0 + 4));
            float4 c = __ldcs((const float4*)(s0 + 8));
            float4 d = __ldcs((const float4*)(s0 + 12));
            float4 e = __ldcs((const float4*)s1);
            float4 f = __ldcs((const float4*)(s1 + 4));
            float4 gg = __ldcs((const float4*)(s1 + 8));
            float4 h = __ldcs((const float4*)(s1 + 12));
            uint4 o0 = make_uint4(pack_bf16(a.x + e.x, a.y + e.y),
                                  pack_bf16(a.z + e.z, a.w + e.w),
                                  pack_bf16(b.x + f.x, b.y + f.y),
                                  pack_bf16(b.z + f.z, b.w + f.w));
            uint4 o1 = make_uint4(pack_bf16(c.x + gg.x, c.y + gg.y),
                                  pack_bf16(c.z + gg.z, c.w + gg.w),
                                  pack_bf16(d.x + h.x, d.y + h.y),
                                  pack_bf16(d.z + h.z, d.w + h.w));
            __stcs((uint4*)dst, o0);
            __stcs((uint4*)(dst + 8), o1);
        }
    }
}

// ---------------- kernel 1: dense MLP (4 batch rows / block) ----------------
__global__ void dense_mlp_kernel(const float* __restrict__ x,
                                 const float* __restrict__ dw0, const float* __restrict__ db0,
                                 const float* __restrict__ dw1, const float* __restrict__ db1,
                                 const float* __restrict__ dw2, const float* __restrict__ db2,
                                 const float* __restrict__ dw3, const float* __restrict__ db3) {
    __shared__ float xs[4][13];
    __shared__ float h0[4][512];
    __shared__ float h1[4][256];
    __shared__ float h2[4][64];
    const int r0 = blockIdx.x * 4;
    const int tid = threadIdx.x;

    if (tid < 52) xs[tid / 13][tid % 13] = x[(r0 + tid / 13) * 13 + tid % 13];
    __syncthreads();

    #pragma unroll
    for (int jj = 0; jj < 2; jj++) {
        int j = tid + jj * 256;
        float a[4];
        float b = db0[j];
        #pragma unroll
        for (int r = 0; r < 4; r++) a[r] = b;
        #pragma unroll
        for (int i = 0; i < 13; i++) {
            float w = dw0[i * 512 + j];
            #pragma unroll
            for (int r = 0; r < 4; r++) a[r] += xs[r][i] * w;
        }
        #pragma unroll
        for (int r = 0; r < 4; r++) h0[r][j] = fmaxf(a[r], 0.f);
    }
    __syncthreads();

    {
        float a[4];
        float b = db1[tid];
        #pragma unroll
        for (int r = 0; r < 4; r++) a[r] = b;
        #pragma unroll 8
        for (int i = 0; i < 512; i++) {
            float w = dw1[i * 256 + tid];
            #pragma unroll
            for (int r = 0; r < 4; r++) a[r] += h0[r][i] * w;
        }
        #pragma unroll
        for (int r = 0; r < 4; r++) h1[r][tid] = fmaxf(a[r], 0.f);
    }
    __syncthreads();

    if (tid < 64) {
        float a[4];
        float b = db2[tid];
        #pragma unroll
        for (int r = 0; r < 4; r++) a[r] = b;
        #pragma unroll 8
        for (int i = 0; i < 256; i++) {
            float w = dw2[i * 64 + tid];
            #pragma unroll
            for (int r = 0; r < 4; r++) a[r] += h1[r][i] * w;
        }
        #pragma unroll
        for (int r = 0; r < 4; r++) h2[r][tid] = fmaxf(a[r], 0.f);
    }
    __syncthreads();

    if (tid < 16) {
        float a[4];
        float b = db3[tid];
        #pragma unroll
        for (int r = 0; r < 4; r++) a[r] = b;
        #pragma unroll
        for (int i = 0; i < 64; i++) {
            float w = dw3[i * 16 + tid];
            #pragma unroll
            for (int r = 0; r < 4; r++) a[r] += h2[r][i] * w;
        }
        #pragma unroll
        for (int r = 0; r < 4; r++) g_z[(size_t)(r0 + r) * 448 + tid] = a[r];
    }
    if (tid >= 64 && tid < 128) {
        int u = tid - 64;
        g_z[(size_t)(r0 + u / 16) * 448 + 432 + (u % 16)] = 0.f;
    }
}

// ---------------- kernel 2: embedding gather -> z[:,16:432] ----------------
__global__ void embed_kernel(const void* __restrict__ sp, const float* __restrict__ emb) {
    int t = blockIdx.x * blockDim.x + threadIdx.x;
    if (t >= 512 * 26) return;
    const int* si = (const int*)sp;
    bool is64 = (si[1] == 0 && si[3] == 0 && si[5] == 0);
    long long v = is64 ? ((const long long*)sp)[t] : (long long)si[t];
    int id = (int)((v + 1) % 100000);
    int b = t / 26, f = t - b * 26;
    const float4* src = (const float4*)(emb + ((size_t)f * 100000 + id) * 16);
    float4* dst = (float4*)(g_z + (size_t)b * 448 + 16 + f * 16);
    dst[0] = src[0]; dst[1] = src[1]; dst[2] = src[2]; dst[3] = src[3];
}

// ---------------- kernel 3: symmetric interaction GEMM ----------------------
// C[b,n] = sum_s A_s @ Bfold_s over the linear packed stream (0.553x HMMA).
// CTA: 128m x 128n; 18 splits (6x188 + 12x186 stages) -> 288 CTAs = 2/SM.
#define BPITCH  272u                        // bytes per staged k-row
#define BTILE   8704u                       // 32 * 272 (one stage)
#define BSTAGE  17408u                      // slot = 2 stages
#define GSMEM   69632u                      // 4-slot ring

__global__ __launch_bounds__(256, 2) void inter_gemm_kernel() {
    extern __shared__ char smem[];
    const uint32_t sb = smem_u32(smem);

    const int tid = threadIdx.x;
    const int warp = tid >> 5, lane = tid & 31;
    const int g = lane >> 2, c = lane & 3;
    const int m0 = blockIdx.x * 128;
    const int n0 = blockIdx.y * 128;
    const int bz = blockIdx.z;
    const int wm0 = (warp >> 2) * 64, wn0 = (warp & 3) * 32;

    const int sA = (bz < 6) ? 188 * bz : 1128 + 186 * (bz - 6);
    const int cnt = (bz < 6) ? 188 : 186;
    const int nslots = cnt >> 1;

    // ---- cp.async params: thread -> (k row, 32B n-chunk) ----
    const int brow = tid >> 3;
    const int bco = (tid & 7) * 16;            // bf16 elems (32B)
    const uint32_t bdst = sb + (uint32_t)(brow * BPITCH + bco * 2);

#define ISSUE_SLOT(T) do {                                                     \
        size_t s_ = (size_t)(sA + 2 * (T));                                    \
        uint32_t d_ = bdst + ((T) & 3) * BSTAGE;                               \
        cpasync32(d_,         g_w0s + s_ * 16384 + brow * 512 + n0 + bco);     \
        cpasync32(d_ + BTILE, g_w0s + (s_ + 1) * 16384 + brow * 512 + n0 + bco); \
    } while (0)

    ISSUE_SLOT(0); CP_COMMIT();
    ISSUE_SLOT(1); CP_COMMIT();
    ISSUE_SLOT(2); CP_COMMIT();

    // ---- consume-side (w, p) tracking ----
    int w = 0;
    while (16 * (w + 1) * (w + 2) <= sA) w++;
    int p = sA - 16 * w * (w + 1);
    int wnext = 16 * (w + 1) * (w + 2);

    // ---- zq register cache: 8 rows x 4 k-pair slots (k = 2c + 8j) ----
    uint32_t zq_c[8][4];
#define LOAD_ZQ(W) do {                                                        \
        _Pragma("unroll")                                                      \
        for (int rr_ = 0; rr_ < 8; rr_++) {                                    \
            int row_ = m0 + wm0 + (rr_ >> 1) * 16 + ((rr_ & 1) << 3) + g;      \
            const float* zr_ = g_z + (size_t)row_ * 448 + (W) * 32 + 2 * c;    \
            _Pragma("unroll")                                                  \
            for (int j_ = 0; j_ < 4; j_++) {                                   \
                float2 v_ = *(const float2*)(zr_ + 8 * j_);                    \
                zq_c[rr_][j_] = pack_bf16(v_.x, v_.y);                         \
            }                                                                  \
        }                                                                      \
    } while (0)

    LOAD_ZQ(w);

    float acc[4][4][4];
    #pragma unroll
    for (int mi = 0; mi < 4; mi++)
        #pragma unroll
        for (int nj = 0; nj < 4; nj++)
            #pragma unroll
            for (int k = 0; k < 4; k++) acc[mi][nj][k] = 0.f;

    const uint32_t b_lrow = (uint32_t)((lane & 15) * BPITCH + ((lane >> 4) & 1) * 16);
    int scons = sA;

    for (int t = 0; t < nslots; t++) {
        CP_WAIT2();
        __syncthreads();                       // slot t visible; buffer (t+3)&3 free
        if (t + 3 < nslots) ISSUE_SLOT(t + 3);
        CP_COMMIT();

        const uint32_t S0 = sb + (uint32_t)((t & 3) * BSTAGE);

        #pragma unroll
        for (int hh = 0; hh < 2; hh++) {
            if (scons == wnext) {              // window boundary (rare)
                w++; wnext += 32 * (w + 1); p = 0;
                LOAD_ZQ(w);
            }
            // zp column p for this warp's 8 m-rows (quad-broadcast LDG, L2-hot)
            float zpv[8];
            #pragma unroll
            for (int rr = 0; rr < 8; rr++) {
                int row = m0 + wm0 + (rr >> 1) * 16 + ((rr & 1) << 3) + g;
                zpv[rr] = __ldg(g_z + (size_t)row * 448 + p);
            }
            const uint32_t B_base = S0 + hh * BTILE;

            #pragma unroll
            for (int ks = 0; ks < 2; ks++) {
                uint32_t bfr[2][4];
                #pragma unroll
                for (int njp = 0; njp < 2; njp++)
                    LDSM4T(bfr[njp][0], bfr[njp][1], bfr[njp][2], bfr[njp][3],
                           B_base + (uint32_t)(ks * 16 * BPITCH + (wn0 + njp * 16) * 2) + b_lrow);

                #pragma unroll
                for (int mi = 0; mi < 4; mi++) {
                    uint32_t zp2a = pack_bf16(zpv[2 * mi], zpv[2 * mi]);
                    uint32_t zp2b = pack_bf16(zpv[2 * mi + 1], zpv[2 * mi + 1]);
                    uint32_t a0 = hmul2(zp2a, zq_c[2 * mi][ks * 2]);
                    uint32_t a1 = hmul2(zp2b, zq_c[2 * mi + 1][ks * 2]);
                    uint32_t a2 = hmul2(zp2a, zq_c[2 * mi][ks * 2 + 1]);
                    uint32_t a3 = hmul2(zp2b, zq_c[2 * mi + 1][ks * 2 + 1]);
                    #pragma unroll
                    for (int nj = 0; nj < 4; nj++) {
                        uint32_t b0 = bfr[nj >> 1][(nj & 1) * 2];
                        uint32_t b1 = bfr[nj >> 1][(nj & 1) * 2 + 1];
                        asm volatile(
                            "mma.sync.aligned.m16n8k16.row.col.f32.bf16.bf16.f32 "
                            "{%0,%1,%2,%3},{%4,%5,%6,%7},{%8,%9},{%0,%1,%2,%3};"
                            : "+f"(acc[mi][nj][0]), "+f"(acc[mi][nj][1]),
                              "+f"(acc[mi][nj][2]), "+f"(acc[mi][nj][3])
                            : "r"(a0), "r"(a1), "r"(a2), "r"(a3),
                              "r"(b0), "r"(b1));
                    }
                }
            }
            p++; scons++;
        }
    }

    // epilogue: write split partials
    #pragma unroll
    for (int mi = 0; mi < 4; mi++)
        #pragma unroll
        for (int nj = 0; nj < 4; nj++) {
            int row = m0 + wm0 + 16 * mi + g;
            int col = n0 + wn0 + 8 * nj + 2 * c;
            float* d0 = g_part + ((size_t)bz * 512 + row) * 512 + col;
            float* d1 = g_part + ((size_t)bz * 512 + row + 8) * 512 + col;
            *(float2*)d0 = make_float2(acc[mi][nj][0], acc[mi][nj][1]);
            *(float2*)d1 = make_float2(acc[mi][nj][2], acc[mi][nj][3]);
        }
}
#undef ISSUE_SLOT
#undef LOAD_ZQ

// ---------------- kernel 4: reduce split-K partials + bias + relu ----------
__global__ void reduce_relu_kernel(const float* __restrict__ pb0) {
    int b = blockIdx.x;
    for (int j = threadIdx.x; j < 512; j += 256) {
        float s = pb0[j];
        #pragma unroll
        for (int sp = 0; sp < 18; sp++)
            s += g_part[((size_t)sp * 512 + b) * 512 + j];
        g_h1[(size_t)b * 512 + j] = fmaxf(s, 0.f);
    }
}

// ---------------- kernel 5: prediction MLP + sigmoid -----------------------
__global__ void pred_kernel(const float* __restrict__ pw1, const float* __restrict__ pb1,
                            const float* __restrict__ pw2, const float* __restrict__ pb2,
                            float* __restrict__ out) {
    __shared__ float h1s[4][512];
    __shared__ float h2s[4][256];
    __shared__ float red[4][8];
    const int r0 = blockIdx.x * 4;
    const int tid = threadIdx.x;

    for (int i = tid; i < 2048; i += 256)
        h1s[i >> 9][i & 511] = g_h1[(size_t)(r0 + (i >> 9)) * 512 + (i & 511)];
    __syncthreads();

    {
        float a[4];
        float b = pb1[tid];
        #pragma unroll
        for (int r = 0; r < 4; r++) a[r] = b;
        #pragma unroll 8
        for (int i = 0; i < 512; i++) {
            float w = pw1[i * 256 + tid];
            #pragma unroll
            for (int r = 0; r < 4; r++) a[r] += h1s[r][i] * w;
        }
        #pragma unroll
        for (int r = 0; r < 4; r++) h2s[r][tid] = fmaxf(a[r], 0.f);
    }
    __syncthreads();

    float w2 = pw2[tid];
    int lane = tid & 31, wp = tid >> 5;
    #pragma unroll
    for (int r = 0; r < 4; r++) {
        float v = h2s[r][tid] * w2;
        #pragma unroll
        for (int o = 16; o; o >>= 1) v += __shfl_xor_sync(0xffffffffu, v, o);
        if (lane == 0) red[r][wp] = v;
    }
    __syncthreads();
    if (tid < 4) {
        float s = pb2[0];
        #pragma unroll
        for (int w = 0; w < 8; w++) s += red[tid][w];
        out[r0 + tid] = 1.f / (1.f + expf(-s));
    }
}

// ---------------- launch ----------------------------------------------------
extern "C" void kernel_launch(void* const* d_in, const int* in_sizes, int n_in,
                              void* d_out, int out_size) {
    const float* x   = (const float*)d_in[0];
    const void*  sp  = d_in[1];
    const float* emb = (const float*)d_in[2];
    const float* dw0 = (const float*)d_in[3];
    const float* db0 = (const float*)d_in[4];
    const float* dw1 = (const float*)d_in[5];
    const float* db1 = (const float*)d_in[6];
    const float* dw2 = (const float*)d_in[7];
    const float* db2 = (const float*)d_in[8];
    const float* dw3 = (const float*)d_in[9];
    const float* db3 = (const float*)d_in[10];
    const float* pw0 = (const float*)d_in[11];
    const float* pb0 = (const float*)d_in[12];
    const float* pw1 = (const float*)d_in[13];
    const float* pb1 = (const float*)d_in[14];
    const float* pw2 = (const float*)d_in[15];
    const float* pb2 = (const float*)d_in[16];
    float* out = (float*)d_out;

    cudaFuncSetAttribute(inter_gemm_kernel,
                         cudaFuncAttributeMaxDynamicSharedMemorySize, (int)GSMEM);

    fold_w0_kernel<<<dim3(112, 14), 256>>>(pw0);
    dense_mlp_kernel<<<128, 256>>>(x, dw0, db0, dw1, db1, dw2, db2, dw3, db3);
    embed_kernel<<<52, 256>>>(sp, emb);
    inter_gemm_kernel<<<dim3(4, 4, 18), 256, GSMEM>>>();
    reduce_relu_kernel<<<512, 256>>>(pb0);
    pred_kernel<<<128, 256>>>(pw1, pb1, pw2, pb2, out);
}

// round 17
// speedup vs baseline: 3.8959x; 1.0424x over previous
#include <cuda_runtime.h>
#include <cuda_bf16.h>
#include <math.h>
#include <stdint.h>

// ---------------- scratch (device globals; no allocs allowed) ----------------
__device__ float g_z[512 * 448];            // z padded to 448 cols (cols 432..447 = 0)
__device__ float g_part[18 * 512 * 512];    // split-K partials
__device__ float g_h1[512 * 512];           // relu(inter@pw0+pb0)
// symmetric-folded W0, window-major packed stream:
// stage s=(w,p), p in [0,32*(w+1)), base 16*w*(w+1); 3360 stages x [32k][512n] bf16
__device__ __nv_bfloat16 g_w0s[(size_t)3360 * 16384];

// pack two fp32 -> bf16x2 (lo -> low half)
__device__ __forceinline__ uint32_t pack_bf16(float lo, float hi) {
    uint32_t r;
    asm("cvt.rn.bf16x2.f32 %0, %1, %2;" : "=r"(r) : "f"(hi), "f"(lo));
    return r;
}
__device__ __forceinline__ uint32_t hmul2(uint32_t a, uint32_t b) {
    uint32_t r;
    asm("mul.rn.bf16x2 %0, %1, %2;" : "=r"(r) : "r"(a), "r"(b));
    return r;
}
__device__ __forceinline__ uint32_t smem_u32(const void* p) {
    uint32_t a;
    asm("{ .reg .u64 t; cvta.to.shared.u64 t, %1; cvt.u32.u64 %0, t; }" : "=r"(a) : "l"(p));
    return a;
}
#define LDSM4T(R0, R1, R2, R3, ADDR)                                           \
    asm volatile("ldmatrix.sync.aligned.m8n8.x4.trans.shared.b16 {%0,%1,%2,%3}, [%4];" \
                 : "=r"(R0), "=r"(R1), "=r"(R2), "=r"(R3) : "r"(ADDR))
__device__ __forceinline__ void cpasync32(uint32_t dst, const void* src) {
    asm volatile(
        "cp.async.cg.shared.global [%0], [%1], 16;\n\t"
        "cp.async.cg.shared.global [%2], [%3], 16;"
        :: "r"(dst), "l"(src), "r"(dst + 16), "l"((const char*)src + 16) : "memory");
}
#define CP_COMMIT() asm volatile("cp.async.commit_group;" ::: "memory")
#define CP_WAIT2()  asm volatile("cp.async.wait_group 2;" ::: "memory")

// ---------------- kernel 0: fold W0 -> symmetric packed bf16 stream ---------
// One-shot blocks (convert-shaped, no loops): grid (448*4, 14).
// Thread -> one 16-elem output chunk of stage (w, p). Reads 64B+64B coalesced
// (warp: 2KB row side + 2KB transpose side), writes 32B. Each W elem read once.
__global__ void fold_w0_kernel(const float* __restrict__ W0) {
    const int w = blockIdx.y;
    const int p = blockIdx.x >> 2;
    if (p >= 32 * (w + 1)) return;             // outside this window's p-range
    const int c = ((blockIdx.x & 3) << 8) | threadIdx.x;   // 0..1023
    const int k = c >> 5;
    const int n = (c & 31) * 16;
    const int q = 32 * w + k;

    __nv_bfloat16* dst = g_w0s + ((size_t)16 * w * (w + 1) + p) * 16384
                               + (size_t)k * 512 + n;

    const bool zero = (p >= 432) || (q > 431) || (((p >> 5) == w) && q < p);
    if (zero) {
        uint4 z = make_uint4(0, 0, 0, 0);
        __stcs((uint4*)dst, z);
        __stcs((uint4*)(dst + 8), z);
    } else if (q == p) {                       // diagonal: W[p,p] once
        const float* s0 = W0 + ((size_t)p * 432 + q) * 512 + n;
        float4 a = __ldcs((const float4*)s0);
        float4 b = __ldcs((const float4*)(s0 + 4));
        float4 cc = __ldcs((const float4*)(s0 + 8));
        float4 d = __ldcs((const float4*)(s0 + 12));
        uint4 o0 = make_uint4(pack_bf16(a.x, a.y), pack_bf16(a.z, a.w),
                              pack_bf16(b.x, b.y), pack_bf16(b.z, b.w));
        uint4 o1 = make_uint4(pack_bf16(cc.x, cc.y), pack_bf16(cc.z, cc.w),
                              pack_bf16(d.x, d.y), pack_bf16(d.z, d.w));
        __stcs((uint4*)dst, o0);
        __stcs((uint4*)(dst + 8), o1);
    } else {                                   // off-diag: W[p,q] + W[q,p]
        const float* s0 = W0 + ((size_t)p * 432 + q) * 512 + n;
        const float* s1 = W0 + ((size_t)q * 432 + p) * 512 + n;
        float4 a = __ldcs((const float4*)s0);
        float4 b = __ldcs((const float4*)(s0 + 4));
        float4 cc = __ldcs((const float4*)(s0 + 8));
        float4 d = __ldcs((const float4*)(s0 + 12));
        float4 e = __ldcs((const float4*)s1);
        float4 f = __ldcs((const float4*)(s1 + 4));
        float4 gg = __ldcs((const float4*)(s1 + 8));
        float4 h = __ldcs((const float4*)(s1 + 12));
        uint4 o0 = make_uint4(pack_bf16(a.x + e.x, a.y + e.y),
                              pack_bf16(a.z + e.z, a.w + e.w),
                              pack_bf16(b.x + f.x, b.y + f.y),
                              pack_bf16(b.z + f.z, b.w + f.w));
        uint4 o1 = make_uint4(pack_bf16(cc.x + gg.x, cc.y + gg.y),
                              pack_bf16(cc.z + gg.z, cc.w + gg.w),
                              pack_bf16(d.x + h.x, d.y + h.y),
                              pack_bf16(d.z + h.z, d.w + h.w));
        __stcs((uint4*)dst, o0);
        __stcs((uint4*)(dst + 8), o1);
    }
}

// ---------------- kernel 1: dense MLP (4 batch rows / block) ----------------
__global__ void dense_mlp_kernel(const float* __restrict__ x,
                                 const float* __restrict__ dw0, const float* __restrict__ db0,
                                 const float* __restrict__ dw1, const float* __restrict__ db1,
                                 const float* __restrict__ dw2, const float* __restrict__ db2,
                                 const float* __restrict__ dw3, const float* __restrict__ db3) {
    __shared__ float xs[4][13];
    __shared__ float h0[4][512];
    __shared__ float h1[4][256];
    __shared__ float h2[4][64];
    const int r0 = blockIdx.x * 4;
    const int tid = threadIdx.x;

    if (tid < 52) xs[tid / 13][tid % 13] = x[(r0 + tid / 13) * 13 + tid % 13];
    __syncthreads();

    #pragma unroll
    for (int jj = 0; jj < 2; jj++) {
        int j = tid + jj * 256;
        float a[4];
        float b = db0[j];
        #pragma unroll
        for (int r = 0; r < 4; r++) a[r] = b;
        #pragma unroll
        for (int i = 0; i < 13; i++) {
            float w = dw0[i * 512 + j];
            #pragma unroll
            for (int r = 0; r < 4; r++) a[r] += xs[r][i] * w;
        }
        #pragma unroll
        for (int r = 0; r < 4; r++) h0[r][j] = fmaxf(a[r], 0.f);
    }
    __syncthreads();

    {
        float a[4];
        float b = db1[tid];
        #pragma unroll
        for (int r = 0; r < 4; r++) a[r] = b;
        #pragma unroll 8
        for (int i = 0; i < 512; i++) {
            float w = dw1[i * 256 + tid];
            #pragma unroll
            for (int r = 0; r < 4; r++) a[r] += h0[r][i] * w;
        }
        #pragma unroll
        for (int r = 0; r < 4; r++) h1[r][tid] = fmaxf(a[r], 0.f);
    }
    __syncthreads();

    if (tid < 64) {
        float a[4];
        float b = db2[tid];
        #pragma unroll
        for (int r = 0; r < 4; r++) a[r] = b;
        #pragma unroll 8
        for (int i = 0; i < 256; i++) {
            float w = dw2[i * 64 + tid];
            #pragma unroll
            for (int r = 0; r < 4; r++) a[r] += h1[r][i] * w;
        }
        #pragma unroll
        for (int r = 0; r < 4; r++) h2[r][tid] = fmaxf(a[r], 0.f);
    }
    __syncthreads();

    if (tid < 16) {
        float a[4];
        float b = db3[tid];
        #pragma unroll
        for (int r = 0; r < 4; r++) a[r] = b;
        #pragma unroll
        for (int i = 0; i < 64; i++) {
            float w = dw3[i * 16 + tid];
            #pragma unroll
            for (int r = 0; r < 4; r++) a[r] += h2[r][i] * w;
        }
        #pragma unroll
        for (int r = 0; r < 4; r++) g_z[(size_t)(r0 + r) * 448 + tid] = a[r];
    }
    if (tid >= 64 && tid < 128) {
        int u = tid - 64;
        g_z[(size_t)(r0 + u / 16) * 448 + 432 + (u % 16)] = 0.f;
    }
}

// ---------------- kernel 2: embedding gather -> z[:,16:432] ----------------
__global__ void embed_kernel(const void* __restrict__ sp, const float* __restrict__ emb) {
    int t = blockIdx.x * blockDim.x + threadIdx.x;
    if (t >= 512 * 26) return;
    const int* si = (const int*)sp;
    bool is64 = (si[1] == 0 && si[3] == 0 && si[5] == 0);
    long long v = is64 ? ((const long long*)sp)[t] : (long long)si[t];
    int id = (int)((v + 1) % 100000);
    int b = t / 26, f = t - b * 26;
    const float4* src = (const float4*)(emb + ((size_t)f * 100000 + id) * 16);
    float4* dst = (float4*)(g_z + (size_t)b * 448 + 16 + f * 16);
    dst[0] = src[0]; dst[1] = src[1]; dst[2] = src[2]; dst[3] = src[3];
}

// ---------------- kernel 3: symmetric interaction GEMM ----------------------
// C[b,n] = sum_s A_s @ Bfold_s over the linear packed stream (0.553x HMMA).
// CTA: 128m x 128n; 18 splits (6x188 + 12x186 stages) -> 288 CTAs = 2/SM.
#define BPITCH  272u                        // bytes per staged k-row
#define BTILE   8704u                       // 32 * 272 (one stage)
#define BSTAGE  17408u                      // slot = 2 stages
#define GSMEM   69632u                      // 4-slot ring

__global__ __launch_bounds__(256, 2) void inter_gemm_kernel() {
    extern __shared__ char smem[];
    const uint32_t sb = smem_u32(smem);

    const int tid = threadIdx.x;
    const int warp = tid >> 5, lane = tid & 31;
    const int g = lane >> 2, c = lane & 3;
    const int m0 = blockIdx.x * 128;
    const int n0 = blockIdx.y * 128;
    const int bz = blockIdx.z;
    const int wm0 = (warp >> 2) * 64, wn0 = (warp & 3) * 32;

    const int sA = (bz < 6) ? 188 * bz : 1128 + 186 * (bz - 6);
    const int cnt = (bz < 6) ? 188 : 186;
    const int nslots = cnt >> 1;

    // ---- cp.async params: thread -> (k row, 32B n-chunk) ----
    const int brow = tid >> 3;
    const int bco = (tid & 7) * 16;            // bf16 elems (32B)
    const uint32_t bdst = sb + (uint32_t)(brow * BPITCH + bco * 2);

#define ISSUE_SLOT(T) do {                                                     \
        size_t s_ = (size_t)(sA + 2 * (T));                                    \
        uint32_t d_ = bdst + ((T) & 3) * BSTAGE;                               \
        cpasync32(d_,         g_w0s + s_ * 16384 + brow * 512 + n0 + bco);     \
        cpasync32(d_ + BTILE, g_w0s + (s_ + 1) * 16384 + brow * 512 + n0 + bco); \
    } while (0)

    ISSUE_SLOT(0); CP_COMMIT();
    ISSUE_SLOT(1); CP_COMMIT();
    ISSUE_SLOT(2); CP_COMMIT();

    // ---- consume-side (w, p) tracking ----
    int w = 0;
    while (16 * (w + 1) * (w + 2) <= sA) w++;
    int p = sA - 16 * w * (w + 1);
    int wnext = 16 * (w + 1) * (w + 2);

    // ---- zq register cache: 8 rows x 4 k-pair slots (k = 2c + 8j) ----
    uint32_t zq_c[8][4];
#define LOAD_ZQ(W) do {                                                        \
        _Pragma("unroll")                                                      \
        for (int rr_ = 0; rr_ < 8; rr_++) {                                    \
            int row_ = m0 + wm0 + (rr_ >> 1) * 16 + ((rr_ & 1) << 3) + g;      \
            const float* zr_ = g_z + (size_t)row_ * 448 + (W) * 32 + 2 * c;    \
            _Pragma("unroll")                                                  \
            for (int j_ = 0; j_ < 4; j_++) {                                   \
                float2 v_ = *(const float2*)(zr_ + 8 * j_);                    \
                zq_c[rr_][j_] = pack_bf16(v_.x, v_.y);                         \
            }                                                                  \
        }                                                                      \
    } while (0)

    LOAD_ZQ(w);

    float acc[4][4][4];
    #pragma unroll
    for (int mi = 0; mi < 4; mi++)
        #pragma unroll
        for (int nj = 0; nj < 4; nj++)
            #pragma unroll
            for (int k = 0; k < 4; k++) acc[mi][nj][k] = 0.f;

    const uint32_t b_lrow = (uint32_t)((lane & 15) * BPITCH + ((lane >> 4) & 1) * 16);
    int scons = sA;

    for (int t = 0; t < nslots; t++) {
        CP_WAIT2();
        __syncthreads();                       // slot t visible; buffer (t+3)&3 free
        if (t + 3 < nslots) ISSUE_SLOT(t + 3);
        CP_COMMIT();

        const uint32_t S0 = sb + (uint32_t)((t & 3) * BSTAGE);

        #pragma unroll
        for (int hh = 0; hh < 2; hh++) {
            if (scons == wnext) {              // window boundary (rare)
                w++; wnext += 32 * (w + 1); p = 0;
                LOAD_ZQ(w);
            }
            // zp column p for this warp's 8 m-rows (quad-broadcast LDG, L2-hot)
            float zpv[8];
            #pragma unroll
            for (int rr = 0; rr < 8; rr++) {
                int row = m0 + wm0 + (rr >> 1) * 16 + ((rr & 1) << 3) + g;
                zpv[rr] = __ldg(g_z + (size_t)row * 448 + p);
            }
            const uint32_t B_base = S0 + hh * BTILE;

            #pragma unroll
            for (int ks = 0; ks < 2; ks++) {
                uint32_t bfr[2][4];
                #pragma unroll
                for (int njp = 0; njp < 2; njp++)
                    LDSM4T(bfr[njp][0], bfr[njp][1], bfr[njp][2], bfr[njp][3],
                           B_base + (uint32_t)(ks * 16 * BPITCH + (wn0 + njp * 16) * 2) + b_lrow);

                #pragma unroll
                for (int mi = 0; mi < 4; mi++) {
                    uint32_t zp2a = pack_bf16(zpv[2 * mi], zpv[2 * mi]);
                    uint32_t zp2b = pack_bf16(zpv[2 * mi + 1], zpv[2 * mi + 1]);
                    uint32_t a0 = hmul2(zp2a, zq_c[2 * mi][ks * 2]);
                    uint32_t a1 = hmul2(zp2b, zq_c[2 * mi + 1][ks * 2]);
                    uint32_t a2 = hmul2(zp2a, zq_c[2 * mi][ks * 2 + 1]);
                    uint32_t a3 = hmul2(zp2b, zq_c[2 * mi + 1][ks * 2 + 1]);
                    #pragma unroll
                    for (int nj = 0; nj < 4; nj++) {
                        uint32_t b0 = bfr[nj >> 1][(nj & 1) * 2];
                        uint32_t b1 = bfr[nj >> 1][(nj & 1) * 2 + 1];
                        asm volatile(
                            "mma.sync.aligned.m16n8k16.row.col.f32.bf16.bf16.f32 "
                            "{%0,%1,%2,%3},{%4,%5,%6,%7},{%8,%9},{%0,%1,%2,%3};"
                            : "+f"(acc[mi][nj][0]), "+f"(acc[mi][nj][1]),
                              "+f"(acc[mi][nj][2]), "+f"(acc[mi][nj][3])
                            : "r"(a0), "r"(a1), "r"(a2), "r"(a3),
                              "r"(b0), "r"(b1));
                    }
                }
            }
            p++; scons++;
        }
    }

    // epilogue: write split partials
    #pragma unroll
    for (int mi = 0; mi < 4; mi++)
        #pragma unroll
        for (int nj = 0; nj < 4; nj++) {
            int row = m0 + wm0 + 16 * mi + g;
            int col = n0 + wn0 + 8 * nj + 2 * c;
            float* d0 = g_part + ((size_t)bz * 512 + row) * 512 + col;
            float* d1 = g_part + ((size_t)bz * 512 + row + 8) * 512 + col;
            *(float2*)d0 = make_float2(acc[mi][nj][0], acc[mi][nj][1]);
            *(float2*)d1 = make_float2(acc[mi][nj][2], acc[mi][nj][3]);
        }
}
#undef ISSUE_SLOT
#undef LOAD_ZQ

// ---------------- kernel 4: reduce split-K partials + bias + relu ----------
__global__ void reduce_relu_kernel(const float* __restrict__ pb0) {
    int b = blockIdx.x;
    for (int j = threadIdx.x; j < 512; j += 256) {
        float s = pb0[j];
        #pragma unroll
        for (int sp = 0; sp < 18; sp++)
            s += g_part[((size_t)sp * 512 + b) * 512 + j];
        g_h1[(size_t)b * 512 + j] = fmaxf(s, 0.f);
    }
}

// ---------------- kernel 5: prediction MLP + sigmoid -----------------------
__global__ void pred_kernel(const float* __restrict__ pw1, const float* __restrict__ pb1,
                            const float* __restrict__ pw2, const float* __restrict__ pb2,
                            float* __restrict__ out) {
    __shared__ float h1s[4][512];
    __shared__ float h2s[4][256];
    __shared__ float red[4][8];
    const int r0 = blockIdx.x * 4;
    const int tid = threadIdx.x;

    for (int i = tid; i < 2048; i += 256)
        h1s[i >> 9][i & 511] = g_h1[(size_t)(r0 + (i >> 9)) * 512 + (i & 511)];
    __syncthreads();

    {
        float a[4];
        float b = pb1[tid];
        #pragma unroll
        for (int r = 0; r < 4; r++) a[r] = b;
        #pragma unroll 8
        for (int i = 0; i < 512; i++) {
            float w = pw1[i * 256 + tid];
            #pragma unroll
            for (int r = 0; r < 4; r++) a[r] += h1s[r][i] * w;
        }
        #pragma unroll
        for (int r = 0; r < 4; r++) h2s[r][tid] = fmaxf(a[r], 0.f);
    }
    __syncthreads();

    float w2 = pw2[tid];
    int lane = tid & 31, wp = tid >> 5;
    #pragma unroll
    for (int r = 0; r < 4; r++) {
        float v = h2s[r][tid] * w2;
        #pragma unroll
        for (int o = 16; o; o >>= 1) v += __shfl_xor_sync(0xffffffffu, v, o);
        if (lane == 0) red[r][wp] = v;
    }
    __syncthreads();
    if (tid < 4) {
        float s = pb2[0];
        #pragma unroll
        for (int w = 0; w < 8; w++) s += red[tid][w];
        out[r0 + tid] = 1.f / (1.f + expf(-s));
    }
}

// ---------------- launch ----------------------------------------------------
extern "C" void kernel_launch(void* const* d_in, const int* in_sizes, int n_in,
                              void* d_out, int out_size) {
    const float* x   = (const float*)d_in[0];
    const void*  sp  = d_in[1];
    const float* emb = (const float*)d_in[2];
    const float* dw0 = (const float*)d_in[3];
    const float* db0 = (const float*)d_in[4];
    const float* dw1 = (const float*)d_in[5];
    const float* db1 = (const float*)d_in[6];
    const float* dw2 = (const float*)d_in[7];
    const float* db2 = (const float*)d_in[8];
    const float* dw3 = (const float*)d_in[9];
    const float* db3 = (const float*)d_in[10];
    const float* pw0 = (const float*)d_in[11];
    const float* pb0 = (const float*)d_in[12];
    const float* pw1 = (const float*)d_in[13];
    const float* pb1 = (const float*)d_in[14];
    const float* pw2 = (const float*)d_in[15];
    const float* pb2 = (const float*)d_in[16];
    float* out = (float*)d_out;

    cudaFuncSetAttribute(inter_gemm_kernel,
                         cudaFuncAttributeMaxDynamicSharedMemorySize, (int)GSMEM);

    fold_w0_kernel<<<dim3(448 * 4, 14), 256>>>(pw0);
    dense_mlp_kernel<<<128, 256>>>(x, dw0, db0, dw1, db1, dw2, db2, dw3, db3);
    embed_kernel<<<52, 256>>>(sp, emb);
    inter_gemm_kernel<<<dim3(4, 4, 18), 256, GSMEM>>>();
    reduce_relu_kernel<<<512, 256>>>(pb0);
    pred_kernel<<<128, 256>>>(pw1, pb1, pw2, pb2, out);
}